// round 1
// baseline (speedup 1.0000x reference)
#include <cuda_runtime.h>

// ---------------------------------------------------------------------------
// CML2DWithStats: 15-step coupled map lattice, fully fused on-chip.
//
// g_{t+1} = clamp( conv3x3( g_t*(1-g_t), K' ) + BETA*drive )
//   with K' = R*(1-BETA)*(EPS*K + (1-EPS)*delta_center)
// Outputs: last, mean(states), var(states), last-drive, last-drive.
//
// One CTA per (batch,channel,strip-of-64-rows). SMEM holds a 96x256 tile
// (64 interior rows + 16-row halo each side). Halo pollution advances 1 row
// per step, so after 15 steps the interior is exact.
// ---------------------------------------------------------------------------

#define R_PARAM  3.9f
#define EPS_P    0.3f
#define BETA_P   0.15f
#define NSTEPS   15
#define CLAMP_LO 1e-4f
#define CLAMP_HI (1.0f - 1e-4f)

constexpr int W      = 256;
constexpr int HIMG   = 256;
constexpr int STRIP  = 64;
constexpr int HALO   = 16;
constexpr int BROWS  = STRIP + 2 * HALO;   // 96 buffer rows
constexpr int TXN    = 64;                 // threads in x (4 px each)
constexpr int TYN    = 8;                  // threads in y
constexpr int KROWS  = BROWS / TYN;        // 12 row-iterations per thread
constexpr int NPLANE = W * HIMG;           // 65536
constexpr long long NTOT = 16LL * 8 * NPLANE;  // 8388608 elems per output tensor

__global__ __launch_bounds__(TXN * TYN, 1)
void cml_fused_kernel(const float* __restrict__ drive,
                      const float* __restrict__ Klocal,
                      float* __restrict__ out)
{
    extern __shared__ float smem[];
    float* A  = smem;               // grid state g
    float* Bm = smem + BROWS * W;   // mapped = g*(1-g)

    const int tx = threadIdx.x;
    const int ty = threadIdx.y;
    const int strip = blockIdx.x;   // 0..3
    const int c     = blockIdx.y;   // 0..7
    const int b     = blockIdx.z;   // 0..15
    const int x0    = tx * 4;
    const int row0  = strip * STRIP - HALO;   // image row of buffer row 0

    // Folded 3x3 kernel: K' = R*(1-BETA)*(EPS*K + (1-EPS)*delta)
    float kk[3][3];
    {
        const float* kc = Klocal + c * 9;
        #pragma unroll
        for (int j = 0; j < 3; ++j)
            #pragma unroll
            for (int i = 0; i < 3; ++i) {
                float v = EPS_P * kc[j * 3 + i];
                if (j == 1 && i == 1) v += (1.0f - EPS_P);
                kk[j][i] = R_PARAM * (1.0f - BETA_P) * v;
            }
    }

    const long long plane_off = (long long)(b * 8 + c) * NPLANE;
    const float* dplane = drive + plane_off;

    // ---- init: A <- drive (in-image rows); Bm <- 0 (out-of-image rows) ----
    #pragma unroll
    for (int k = 0; k < KROWS; ++k) {
        int r  = ty + TYN * k;
        int ir = row0 + r;
        if ((unsigned)ir < (unsigned)HIMG) {
            float4 d4 = *reinterpret_cast<const float4*>(dplane + (long long)ir * W + x0);
            *reinterpret_cast<float4*>(A + r * W + x0) = d4;
        } else {
            *reinterpret_cast<float4*>(Bm + r * W + x0) = make_float4(0.f, 0.f, 0.f, 0.f);
        }
    }
    __syncthreads();

    // per-thread stats accumulators for the 8 interior row-iters (k = 2..9)
    float sum[8][4];
    float ssq[8][4];
    #pragma unroll
    for (int k = 0; k < 8; ++k)
        #pragma unroll
        for (int i = 0; i < 4; ++i) { sum[k][i] = 0.f; ssq[k][i] = 0.f; }

    #pragma unroll 1
    for (int step = 0; step < NSTEPS; ++step) {
        // ---- pass 1: Bm <- g*(1-g) for in-image rows ----
        #pragma unroll
        for (int k = 0; k < KROWS; ++k) {
            int r  = ty + TYN * k;
            int ir = row0 + r;
            if ((unsigned)ir < (unsigned)HIMG) {
                float4 g = *reinterpret_cast<float4*>(A + r * W + x0);
                float4 m;
                m.x = g.x * (1.0f - g.x);
                m.y = g.y * (1.0f - g.y);
                m.z = g.z * (1.0f - g.z);
                m.w = g.w * (1.0f - g.w);
                *reinterpret_cast<float4*>(Bm + r * W + x0) = m;
            }
        }
        __syncthreads();

        // ---- pass 2: A <- clamp(conv3x3(Bm, K') + BETA*drive) ----
        #pragma unroll
        for (int k = 0; k < KROWS; ++k) {
            int r  = ty + TYN * k;
            int ir = row0 + r;
            if ((unsigned)ir < (unsigned)HIMG) {
                float acc0, acc1, acc2, acc3;
                {
                    float4 d4 = *reinterpret_cast<const float4*>(dplane + (long long)ir * W + x0);
                    acc0 = BETA_P * d4.x;
                    acc1 = BETA_P * d4.y;
                    acc2 = BETA_P * d4.z;
                    acc3 = BETA_P * d4.w;
                }
                #pragma unroll
                for (int j = 0; j < 3; ++j) {
                    int rr = r + j - 1;
                    float w0, w1, w2, w3, w4, w5;
                    if ((unsigned)rr < (unsigned)BROWS) {
                        const float* rp = Bm + rr * W;
                        float4 cc = *reinterpret_cast<const float4*>(rp + x0);
                        w1 = cc.x; w2 = cc.y; w3 = cc.z; w4 = cc.w;
                        w0 = (tx > 0)       ? rp[x0 - 1] : 0.f;
                        w5 = (tx < TXN - 1) ? rp[x0 + 4] : 0.f;
                    } else {
                        w0 = w1 = w2 = w3 = w4 = w5 = 0.f;
                    }
                    acc0 = fmaf(kk[j][0], w0, fmaf(kk[j][1], w1, fmaf(kk[j][2], w2, acc0)));
                    acc1 = fmaf(kk[j][0], w1, fmaf(kk[j][1], w2, fmaf(kk[j][2], w3, acc1)));
                    acc2 = fmaf(kk[j][0], w2, fmaf(kk[j][1], w3, fmaf(kk[j][2], w4, acc2)));
                    acc3 = fmaf(kk[j][0], w3, fmaf(kk[j][1], w4, fmaf(kk[j][2], w5, acc3)));
                }
                float4 g;
                g.x = fminf(fmaxf(acc0, CLAMP_LO), CLAMP_HI);
                g.y = fminf(fmaxf(acc1, CLAMP_LO), CLAMP_HI);
                g.z = fminf(fmaxf(acc2, CLAMP_LO), CLAMP_HI);
                g.w = fminf(fmaxf(acc3, CLAMP_LO), CLAMP_HI);
                *reinterpret_cast<float4*>(A + r * W + x0) = g;

                if (k >= 2 && k <= 9) {       // interior rows: accumulate stats
                    sum[k - 2][0] += g.x;  ssq[k - 2][0] = fmaf(g.x, g.x, ssq[k - 2][0]);
                    sum[k - 2][1] += g.y;  ssq[k - 2][1] = fmaf(g.y, g.y, ssq[k - 2][1]);
                    sum[k - 2][2] += g.z;  ssq[k - 2][2] = fmaf(g.z, g.z, ssq[k - 2][2]);
                    sum[k - 2][3] += g.w;  ssq[k - 2][3] = fmaf(g.w, g.w, ssq[k - 2][3]);
                }
            }
        }
        __syncthreads();
    }

    // ---- epilogue: write 5 output tensors for interior rows ----
    const float inv = 1.0f / (float)NSTEPS;
    #pragma unroll
    for (int k = 2; k <= 9; ++k) {
        int r  = ty + TYN * k;
        int ir = row0 + r;                  // always in [0,256)
        long long idx = plane_off + (long long)ir * W + x0;

        float4 last4 = *reinterpret_cast<float4*>(A + r * W + x0);
        float4 d4    = *reinterpret_cast<const float4*>(dplane + (long long)ir * W + x0);

        float4 mean4, var4, del4;
        mean4.x = sum[k - 2][0] * inv;
        mean4.y = sum[k - 2][1] * inv;
        mean4.z = sum[k - 2][2] * inv;
        mean4.w = sum[k - 2][3] * inv;
        var4.x = fmaf(-mean4.x, mean4.x, ssq[k - 2][0] * inv);
        var4.y = fmaf(-mean4.y, mean4.y, ssq[k - 2][1] * inv);
        var4.z = fmaf(-mean4.z, mean4.z, ssq[k - 2][2] * inv);
        var4.w = fmaf(-mean4.w, mean4.w, ssq[k - 2][3] * inv);
        del4.x = last4.x - d4.x;
        del4.y = last4.y - d4.y;
        del4.z = last4.z - d4.z;
        del4.w = last4.w - d4.w;

        *reinterpret_cast<float4*>(out + idx)             = last4;
        *reinterpret_cast<float4*>(out + NTOT + idx)      = mean4;
        *reinterpret_cast<float4*>(out + 2 * NTOT + idx)  = var4;
        *reinterpret_cast<float4*>(out + 3 * NTOT + idx)  = del4;
        *reinterpret_cast<float4*>(out + 4 * NTOT + idx)  = del4;   // last_drive == delta
    }
}

extern "C" void kernel_launch(void* const* d_in, const int* in_sizes, int n_in,
                              void* d_out, int out_size)
{
    const float* drive  = (const float*)d_in[0];   // [16,8,256,256] f32
    const float* Klocal = (const float*)d_in[1];   // [8,1,3,3] f32
    float* out = (float*)d_out;                    // 5 x [16,8,256,256] f32

    const int smem_bytes = 2 * BROWS * W * (int)sizeof(float);   // 196608
    cudaFuncSetAttribute(cml_fused_kernel,
                         cudaFuncAttributeMaxDynamicSharedMemorySize, smem_bytes);

    dim3 grid(HIMG / STRIP, 8, 16);   // (strip, channel, batch) = (4,8,16) = 512 CTAs
    dim3 block(TXN, TYN);             // 512 threads
    cml_fused_kernel<<<grid, block, smem_bytes>>>(drive, Klocal, out);
}

// round 2
// speedup vs baseline: 1.8698x; 1.8698x over previous
#include <cuda_runtime.h>

// ---------------------------------------------------------------------------
// CML2DWithStats, round 2: ping-pong the MAPPED field, shuffle-based
// horizontal halo, conflict-free split-quad smem layout, shrinking window.
//
//   g_{t+1} = clamp( conv3x3( m_t, K' ) + BETA*drive ),  m = g*(1-g)
//   K' = R*(1-BETA)*(EPS*K + (1-EPS)*delta_center)
//
// One CTA per (batch, channel, 64-row strip). SMEM = two 96x256 mapped
// buffers. Buffer rows 0..95 = image rows strip*64-16 .. +79.
// Correctness window: after step t (0-indexed) rows [2+t, 93-t] are exact;
// step t computes exactly that range (reads [1+t, 94-t], written by t-1).
// Out-of-image rows stay 0 in both buffers forever => zero padding.
//
// SMEM row layout (split-quad): row*256 + [quadA(tx)*4 .. | 128 + quadB(tx)*4]
// so every LDS.128 / STS.128 has 16B lane stride => conflict-free.
// ---------------------------------------------------------------------------

#define R_PARAM  3.9f
#define EPS_P    0.3f
#define BETA_P   0.15f
#define NSTEPS   15
#define CLAMP_LO 1e-4f
#define CLAMP_HI (1.0f - 1e-4f)

constexpr int W      = 256;
constexpr int HIMG   = 256;
constexpr int STRIP  = 64;
constexpr int HALO   = 16;
constexpr int BROWS  = 96;
constexpr int TXN    = 32;     // warp spans full row, 8 px per thread
constexpr int TYN    = 16;
constexpr int NTHR   = TXN * TYN;  // 512
constexpr int NPLANE = W * HIMG;
constexpr long long NTOT = 16LL * 8 * NPLANE;

__device__ __forceinline__ float clampg(float v) {
    return fminf(fmaxf(v, CLAMP_LO), CLAMP_HI);
}

__global__ __launch_bounds__(NTHR, 1)
void cml_fused_kernel(const float* __restrict__ drive,
                      const float* __restrict__ Klocal,
                      float* __restrict__ out)
{
    extern __shared__ float sm[];
    float* MB0 = sm;
    float* MB1 = sm + BROWS * W;

    const int tx = threadIdx.x;
    const int ty = threadIdx.y;
    const int strip = blockIdx.x;
    const int c     = blockIdx.y;
    const int b     = blockIdx.z;
    const int row0  = strip * STRIP - HALO;
    const int x4    = tx * 4;      // quad offset inside each half-region
    const int x0    = tx * 8;      // global x of first pixel

    // Folded kernel K' = R*(1-BETA)*(EPS*K + (1-EPS)*delta)
    float kk[3][3];
    {
        const float* kc = Klocal + c * 9;
        #pragma unroll
        for (int j = 0; j < 3; ++j)
            #pragma unroll
            for (int i = 0; i < 3; ++i) {
                float v = EPS_P * kc[j * 3 + i];
                if (j == 1 && i == 1) v += (1.0f - EPS_P);
                kk[j][i] = R_PARAM * (1.0f - BETA_P) * v;
            }
    }

    const long long plane = (long long)(b * 8 + c) * NPLANE;
    const float* dpl = drive + plane;

    // ---- init: MB0 <- mapped(drive) on in-image rows, 0 elsewhere; MB1 <- 0 ----
    #pragma unroll
    for (int k = 0; k < 6; ++k) {
        int r  = ty + TYN * k;
        int ir = row0 + r;
        float* p0 = MB0 + r * W;
        float* p1 = MB1 + r * W;
        float4 z = make_float4(0.f, 0.f, 0.f, 0.f);
        *reinterpret_cast<float4*>(p1 + x4)       = z;
        *reinterpret_cast<float4*>(p1 + 128 + x4) = z;
        if ((unsigned)ir < (unsigned)HIMG) {
            const float* dr = dpl + (long long)ir * W + x0;
            float4 dA = *reinterpret_cast<const float4*>(dr);
            float4 dB = *reinterpret_cast<const float4*>(dr + 4);
            float4 mA, mB;
            mA.x = fmaf(-dA.x, dA.x, dA.x);  mA.y = fmaf(-dA.y, dA.y, dA.y);
            mA.z = fmaf(-dA.z, dA.z, dA.z);  mA.w = fmaf(-dA.w, dA.w, dA.w);
            mB.x = fmaf(-dB.x, dB.x, dB.x);  mB.y = fmaf(-dB.y, dB.y, dB.y);
            mB.z = fmaf(-dB.z, dB.z, dB.z);  mB.w = fmaf(-dB.w, dB.w, dB.w);
            *reinterpret_cast<float4*>(p0 + x4)       = mA;
            *reinterpret_cast<float4*>(p0 + 128 + x4) = mB;
        } else {
            *reinterpret_cast<float4*>(p0 + x4)       = z;
            *reinterpret_cast<float4*>(p0 + 128 + x4) = z;
        }
    }
    __syncthreads();

    // stats accumulators: interior iters k=1..4 (buffer rows 16..79)
    float sum[4][8], ssq[4][8];
    #pragma unroll
    for (int s = 0; s < 4; ++s)
        #pragma unroll
        for (int i = 0; i < 8; ++i) { sum[s][i] = 0.f; ssq[s][i] = 0.f; }

    // conv + clamp for one row; acc preloaded with BETA*drive
    #define CONV_ROW(Min, r, acc)                                              \
        {                                                                      \
            _Pragma("unroll")                                                  \
            for (int j = 0; j < 3; ++j) {                                      \
                const float* rp = (Min) + ((r) - 1 + j) * W;                   \
                float4 qa = *reinterpret_cast<const float4*>(rp + x4);         \
                float4 qb = *reinterpret_cast<const float4*>(rp + 128 + x4);   \
                float m0 = qa.x, m1 = qa.y, m2 = qa.z, m3 = qa.w;              \
                float m4 = qb.x, m5 = qb.y, m6 = qb.z, m7 = qb.w;              \
                float lm = __shfl_up_sync(0xffffffffu, m7, 1);                 \
                float rm = __shfl_down_sync(0xffffffffu, m0, 1);               \
                if (tx == 0)  lm = 0.f;                                        \
                if (tx == 31) rm = 0.f;                                        \
                float c0 = kk[j][0], c1 = kk[j][1], c2 = kk[j][2];             \
                acc[0] = fmaf(c0, lm, fmaf(c1, m0, fmaf(c2, m1, acc[0])));     \
                acc[1] = fmaf(c0, m0, fmaf(c1, m1, fmaf(c2, m2, acc[1])));     \
                acc[2] = fmaf(c0, m1, fmaf(c1, m2, fmaf(c2, m3, acc[2])));     \
                acc[3] = fmaf(c0, m2, fmaf(c1, m3, fmaf(c2, m4, acc[3])));     \
                acc[4] = fmaf(c0, m3, fmaf(c1, m4, fmaf(c2, m5, acc[4])));     \
                acc[5] = fmaf(c0, m4, fmaf(c1, m5, fmaf(c2, m6, acc[5])));     \
                acc[6] = fmaf(c0, m5, fmaf(c1, m6, fmaf(c2, m7, acc[6])));     \
                acc[7] = fmaf(c0, m6, fmaf(c1, m7, fmaf(c2, rm, acc[7])));     \
            }                                                                  \
        }

    // ---- steps 0..13: conv -> g -> map -> store ----
    #pragma unroll 1
    for (int t = 0; t < NSTEPS - 1; ++t) {
        const float* Min  = (t & 1) ? MB1 : MB0;
        float*       Mout = (t & 1) ? MB0 : MB1;
        const int lo = 2 + t, hi = 93 - t;

        #pragma unroll
        for (int k = 0; k < 6; ++k) {
            int r  = ty + TYN * k;
            int ir = row0 + r;
            if (r < lo || r > hi || (unsigned)ir >= (unsigned)HIMG) continue;

            const float* dr = dpl + (long long)ir * W + x0;
            float4 dA = *reinterpret_cast<const float4*>(dr);
            float4 dB = *reinterpret_cast<const float4*>(dr + 4);
            float acc[8];
            acc[0] = BETA_P * dA.x;  acc[1] = BETA_P * dA.y;
            acc[2] = BETA_P * dA.z;  acc[3] = BETA_P * dA.w;
            acc[4] = BETA_P * dB.x;  acc[5] = BETA_P * dB.y;
            acc[6] = BETA_P * dB.z;  acc[7] = BETA_P * dB.w;

            CONV_ROW(Min, r, acc)

            float g[8], mm[8];
            #pragma unroll
            for (int i = 0; i < 8; ++i) {
                g[i]  = clampg(acc[i]);
                mm[i] = fmaf(-g[i], g[i], g[i]);
            }
            float* op = Mout + r * W;
            *reinterpret_cast<float4*>(op + x4)       = make_float4(mm[0], mm[1], mm[2], mm[3]);
            *reinterpret_cast<float4*>(op + 128 + x4) = make_float4(mm[4], mm[5], mm[6], mm[7]);

            if (k >= 1 && k <= 4) {
                int si = k - 1;
                #pragma unroll
                for (int i = 0; i < 8; ++i) {
                    sum[si][i] += g[i];
                    ssq[si][i]  = fmaf(g[i], g[i], ssq[si][i]);
                }
            }
        }
        __syncthreads();
    }

    // ---- final step t=14: interior only, write all 5 outputs ----
    {
        const float* Min = ((NSTEPS - 1) & 1) ? MB1 : MB0;   // NSTEPS-1 = 14 even -> MB0
        const float inv = 1.0f / (float)NSTEPS;

        #pragma unroll
        for (int k = 1; k <= 4; ++k) {
            int r  = ty + TYN * k;       // 16..79 (always in-image, in-window)
            int ir = row0 + r;
            const float* dr = dpl + (long long)ir * W + x0;
            float4 dA = *reinterpret_cast<const float4*>(dr);
            float4 dB = *reinterpret_cast<const float4*>(dr + 4);
            float dv[8] = { dA.x, dA.y, dA.z, dA.w, dB.x, dB.y, dB.z, dB.w };

            float acc[8];
            #pragma unroll
            for (int i = 0; i < 8; ++i) acc[i] = BETA_P * dv[i];

            CONV_ROW(Min, r, acc)

            int si = k - 1;
            float g[8], mean[8], var[8], del[8];
            #pragma unroll
            for (int i = 0; i < 8; ++i) {
                g[i] = clampg(acc[i]);
                float s  = sum[si][i] + g[i];
                float sq = fmaf(g[i], g[i], ssq[si][i]);
                mean[i] = s * inv;
                var[i]  = fmaf(-mean[i], mean[i], sq * inv);
                del[i]  = g[i] - dv[i];
            }

            long long idx = plane + (long long)ir * W + x0;
            *reinterpret_cast<float4*>(out + idx)                = make_float4(g[0], g[1], g[2], g[3]);
            *reinterpret_cast<float4*>(out + idx + 4)            = make_float4(g[4], g[5], g[6], g[7]);
            *reinterpret_cast<float4*>(out + NTOT + idx)         = make_float4(mean[0], mean[1], mean[2], mean[3]);
            *reinterpret_cast<float4*>(out + NTOT + idx + 4)     = make_float4(mean[4], mean[5], mean[6], mean[7]);
            *reinterpret_cast<float4*>(out + 2 * NTOT + idx)     = make_float4(var[0], var[1], var[2], var[3]);
            *reinterpret_cast<float4*>(out + 2 * NTOT + idx + 4) = make_float4(var[4], var[5], var[6], var[7]);
            *reinterpret_cast<float4*>(out + 3 * NTOT + idx)     = make_float4(del[0], del[1], del[2], del[3]);
            *reinterpret_cast<float4*>(out + 3 * NTOT + idx + 4) = make_float4(del[4], del[5], del[6], del[7]);
            *reinterpret_cast<float4*>(out + 4 * NTOT + idx)     = make_float4(del[0], del[1], del[2], del[3]);
            *reinterpret_cast<float4*>(out + 4 * NTOT + idx + 4) = make_float4(del[4], del[5], del[6], del[7]);
        }
    }
    #undef CONV_ROW
}

extern "C" void kernel_launch(void* const* d_in, const int* in_sizes, int n_in,
                              void* d_out, int out_size)
{
    const float* drive  = (const float*)d_in[0];   // [16,8,256,256] f32
    const float* Klocal = (const float*)d_in[1];   // [8,1,3,3] f32
    float* out = (float*)d_out;                    // 5 x [16,8,256,256] f32

    const int smem_bytes = 2 * BROWS * W * (int)sizeof(float);   // 196608
    cudaFuncSetAttribute(cml_fused_kernel,
                         cudaFuncAttributeMaxDynamicSharedMemorySize, smem_bytes);

    dim3 grid(HIMG / STRIP, 8, 16);    // 4 strips x 8 ch x 16 batch = 512 CTAs
    dim3 block(TXN, TYN);              // 512 threads
    cml_fused_kernel<<<grid, block, smem_bytes>>>(drive, Klocal, out);
}

// round 3
// speedup vs baseline: 1.9114x; 1.0222x over previous
#include <cuda_runtime.h>

// ---------------------------------------------------------------------------
// CML2DWithStats, round 3: paired-row processing for vertical LDS reuse.
//
//   g_{t+1} = clamp( conv3x3( m_t, K' ) + BETA*drive ),  m = g*(1-g)
//   K' = R*(1-BETA)*(EPS*K + (1-EPS)*delta_center)
//
// One CTA per (batch, channel, 64-row strip). SMEM = two 96x256 mapped
// buffers (split-quad layout: row*256 + [tx*4 | 128 + tx*4], conflict-free).
// Each thread owns 3 row-PAIRS (p = ty + 16k, rows 2p, 2p+1): a pair loads
// 4 input rows for 2 outputs -> 4 LDS.128 + 4 SHFL per row (was 6+6).
// Interior rows 16..79 = exactly 2 interior pairs per thread (uniform stats).
// Shrinking window: step t computes rows [2+t, 93-t]; pairs straddling the
// window edge are computed wholly (stale edge rows never read later).
// ---------------------------------------------------------------------------

#define R_PARAM  3.9f
#define EPS_P    0.3f
#define BETA_P   0.15f
#define NSTEPS   15
#define CLAMP_LO 1e-4f
#define CLAMP_HI (1.0f - 1e-4f)

constexpr int W      = 256;
constexpr int HIMG   = 256;
constexpr int STRIP  = 64;
constexpr int HALO   = 16;
constexpr int BROWS  = 96;
constexpr int TXN    = 32;
constexpr int TYN    = 16;
constexpr int NTHR   = TXN * TYN;          // 512
constexpr int NPLANE = W * HIMG;
constexpr long long NTOT = 16LL * 8 * NPLANE;

__device__ __forceinline__ float clampg(float v) {
    return fminf(fmaxf(v, CLAMP_LO), CLAMP_HI);
}

__global__ __launch_bounds__(NTHR, 1)
void cml_fused_kernel(const float* __restrict__ drive,
                      const float* __restrict__ Klocal,
                      float* __restrict__ out)
{
    extern __shared__ float sm[];
    float* MB0 = sm;
    float* MB1 = sm + BROWS * W;

    const int tx = threadIdx.x;
    const int ty = threadIdx.y;
    const int strip = blockIdx.x;
    const int c     = blockIdx.y;
    const int b     = blockIdx.z;
    const int row0  = strip * STRIP - HALO;
    const int x4    = tx * 4;
    const int x0    = tx * 8;

    // Folded kernel K' = R*(1-BETA)*(EPS*K + (1-EPS)*delta)
    float kk[3][3];
    {
        const float* kc = Klocal + c * 9;
        #pragma unroll
        for (int j = 0; j < 3; ++j)
            #pragma unroll
            for (int i = 0; i < 3; ++i) {
                float v = EPS_P * kc[j * 3 + i];
                if (j == 1 && i == 1) v += (1.0f - EPS_P);
                kk[j][i] = R_PARAM * (1.0f - BETA_P) * v;
            }
    }

    const long long plane = (long long)(b * 8 + c) * NPLANE;
    const float* dpl = drive + plane;

    // ---- init: MB0 <- mapped(drive) on in-image rows, 0 elsewhere; MB1 <- 0 ----
    #pragma unroll
    for (int k = 0; k < 6; ++k) {
        int r  = ty + TYN * k;
        int ir = row0 + r;
        float* p0 = MB0 + r * W;
        float* p1 = MB1 + r * W;
        float4 z = make_float4(0.f, 0.f, 0.f, 0.f);
        *reinterpret_cast<float4*>(p1 + x4)       = z;
        *reinterpret_cast<float4*>(p1 + 128 + x4) = z;
        if ((unsigned)ir < (unsigned)HIMG) {
            const float* dr = dpl + (long long)ir * W + x0;
            float4 dA = *reinterpret_cast<const float4*>(dr);
            float4 dB = *reinterpret_cast<const float4*>(dr + 4);
            float4 mA, mB;
            mA.x = fmaf(-dA.x, dA.x, dA.x);  mA.y = fmaf(-dA.y, dA.y, dA.y);
            mA.z = fmaf(-dA.z, dA.z, dA.z);  mA.w = fmaf(-dA.w, dA.w, dA.w);
            mB.x = fmaf(-dB.x, dB.x, dB.x);  mB.y = fmaf(-dB.y, dB.y, dB.y);
            mB.z = fmaf(-dB.z, dB.z, dB.z);  mB.w = fmaf(-dB.w, dB.w, dB.w);
            *reinterpret_cast<float4*>(p0 + x4)       = mA;
            *reinterpret_cast<float4*>(p0 + 128 + x4) = mB;
        } else {
            *reinterpret_cast<float4*>(p0 + x4)       = z;
            *reinterpret_cast<float4*>(p0 + 128 + x4) = z;
        }
    }
    __syncthreads();

    // stats: 2 interior pairs per thread. slot layout: [row-in-pair*8 + i]
    float sum0[16], ssq0[16], sum1[16], ssq1[16];
    #pragma unroll
    for (int i = 0; i < 16; ++i) {
        sum0[i] = 0.f; ssq0[i] = 0.f; sum1[i] = 0.f; ssq1[i] = 0.f;
    }

    // accumulate one loaded row (m0..m7,lm,rm live) into acc with kernel row cc
    #define ACCROW(acc, cc)                                                    \
        {                                                                      \
            float c0 = (cc)[0], c1 = (cc)[1], c2 = (cc)[2];                    \
            acc[0] = fmaf(c0, lm, fmaf(c1, m0, fmaf(c2, m1, acc[0])));         \
            acc[1] = fmaf(c0, m0, fmaf(c1, m1, fmaf(c2, m2, acc[1])));         \
            acc[2] = fmaf(c0, m1, fmaf(c1, m2, fmaf(c2, m3, acc[2])));         \
            acc[3] = fmaf(c0, m2, fmaf(c1, m3, fmaf(c2, m4, acc[3])));         \
            acc[4] = fmaf(c0, m3, fmaf(c1, m4, fmaf(c2, m5, acc[4])));         \
            acc[5] = fmaf(c0, m4, fmaf(c1, m5, fmaf(c2, m6, acc[5])));         \
            acc[6] = fmaf(c0, m5, fmaf(c1, m6, fmaf(c2, m7, acc[6])));         \
            acc[7] = fmaf(c0, m6, fmaf(c1, m7, fmaf(c2, rm, acc[7])));         \
        }

    // conv for a pair of rows r0,r0+1: loads rows r0-1..r0+2 once each
    #define PAIR_CONV(Min, r0, acc0, acc1)                                     \
        {                                                                      \
            _Pragma("unroll")                                                  \
            for (int jr = 0; jr < 4; ++jr) {                                   \
                const float* rp = (Min) + ((r0) - 1 + jr) * W;                 \
                float4 qa = *reinterpret_cast<const float4*>(rp + x4);         \
                float4 qb = *reinterpret_cast<const float4*>(rp + 128 + x4);   \
                float m0 = qa.x, m1 = qa.y, m2 = qa.z, m3 = qa.w;              \
                float m4 = qb.x, m5 = qb.y, m6 = qb.z, m7 = qb.w;              \
                float lm = __shfl_up_sync(0xffffffffu, m7, 1);                 \
                float rm = __shfl_down_sync(0xffffffffu, m0, 1);               \
                if (tx == 0)  lm = 0.f;                                        \
                if (tx == 31) rm = 0.f;                                        \
                if (jr < 3) ACCROW(acc0, kk[jr])                               \
                if (jr > 0) ACCROW(acc1, kk[jr - 1])                           \
            }                                                                  \
        }

    #define LOAD_DRIVE_ACC(ir, acc)                                            \
        {                                                                      \
            const float* dr = dpl + (long long)(ir) * W + x0;                  \
            float4 dA = *reinterpret_cast<const float4*>(dr);                  \
            float4 dB = *reinterpret_cast<const float4*>(dr + 4);              \
            acc[0] = BETA_P * dA.x;  acc[1] = BETA_P * dA.y;                   \
            acc[2] = BETA_P * dA.z;  acc[3] = BETA_P * dA.w;                   \
            acc[4] = BETA_P * dB.x;  acc[5] = BETA_P * dB.y;                   \
            acc[6] = BETA_P * dB.z;  acc[7] = BETA_P * dB.w;                   \
        }

    #define STATS_ADD(sumA, ssqA, g0, g1)                                      \
        {                                                                      \
            _Pragma("unroll")                                                  \
            for (int i = 0; i < 8; ++i) {                                      \
                sumA[i]     += g0[i];  ssqA[i]     = fmaf(g0[i], g0[i], ssqA[i]); \
                sumA[i + 8] += g1[i];  ssqA[i + 8] = fmaf(g1[i], g1[i], ssqA[i + 8]); \
            }                                                                  \
        }

    // ---- steps 0..13 ----
    #pragma unroll 1
    for (int t = 0; t < NSTEPS - 1; ++t) {
        const float* Min  = (t & 1) ? MB1 : MB0;
        float*       Mout = (t & 1) ? MB0 : MB1;
        const int lo = 2 + t, hi = 93 - t;

        #pragma unroll
        for (int k = 0; k < 3; ++k) {
            const int p  = ty + 16 * k;
            const int r0 = 2 * p;
            const int r1 = r0 + 1;
            const int ir0 = row0 + r0;
            if (r1 < lo || r0 > hi) continue;                    // outside window
            if ((unsigned)ir0 >= (unsigned)HIMG) continue;       // out of image (pair-aligned)

            float acc0[8], acc1[8];
            LOAD_DRIVE_ACC(ir0, acc0)
            LOAD_DRIVE_ACC(ir0 + 1, acc1)

            PAIR_CONV(Min, r0, acc0, acc1)

            float g0[8], g1[8], mm0[8], mm1[8];
            #pragma unroll
            for (int i = 0; i < 8; ++i) {
                g0[i]  = clampg(acc0[i]);
                g1[i]  = clampg(acc1[i]);
                mm0[i] = fmaf(-g0[i], g0[i], g0[i]);
                mm1[i] = fmaf(-g1[i], g1[i], g1[i]);
            }
            float* op0 = Mout + r0 * W;
            float* op1 = Mout + r1 * W;
            *reinterpret_cast<float4*>(op0 + x4)       = make_float4(mm0[0], mm0[1], mm0[2], mm0[3]);
            *reinterpret_cast<float4*>(op0 + 128 + x4) = make_float4(mm0[4], mm0[5], mm0[6], mm0[7]);
            *reinterpret_cast<float4*>(op1 + x4)       = make_float4(mm1[0], mm1[1], mm1[2], mm1[3]);
            *reinterpret_cast<float4*>(op1 + 128 + x4) = make_float4(mm1[4], mm1[5], mm1[6], mm1[7]);

            // stats: interior pairs (rows 16..79). ty<8 -> k 1,2 ; ty>=8 -> k 0,1
            if (k == 0) {
                if (ty >= 8) STATS_ADD(sum0, ssq0, g0, g1)
            } else if (k == 1) {
                if (ty < 8) { STATS_ADD(sum0, ssq0, g0, g1) }
                else        { STATS_ADD(sum1, ssq1, g0, g1) }
            } else {
                if (ty < 8) STATS_ADD(sum1, ssq1, g0, g1)
            }
        }
        __syncthreads();
    }

    // ---- final step t=14: interior pairs only, write all 5 outputs ----
    {
        const float* Min = MB0;                 // t=14 even -> read MB0
        const float inv = 1.0f / (float)NSTEPS;

        #pragma unroll
        for (int k = 0; k < 3; ++k) {
            // interior condition mirrors the stats mapping
            bool inter0 = (k == 0 && ty >= 8) || (k == 1 && ty < 8);
            bool inter1 = (k == 1 && ty >= 8) || (k == 2 && ty < 8);
            if (!inter0 && !inter1) continue;
            float* sumA = inter0 ? sum0 : sum1;
            float* ssqA = inter0 ? ssq0 : ssq1;

            const int p  = ty + 16 * k;
            const int r0 = 2 * p;
            const int ir0 = row0 + r0;

            float acc0[8], acc1[8];
            LOAD_DRIVE_ACC(ir0, acc0)
            LOAD_DRIVE_ACC(ir0 + 1, acc1)
            // stash drive (rebuild from acc before conv): dv = acc/BETA
            float dv0[8], dv1[8];
            #pragma unroll
            for (int i = 0; i < 8; ++i) {
                dv0[i] = acc0[i] * (1.0f / BETA_P);
                dv1[i] = acc1[i] * (1.0f / BETA_P);
            }

            PAIR_CONV(Min, r0, acc0, acc1)

            #pragma unroll
            for (int half = 0; half < 2; ++half) {
                const float* acc = half ? acc1 : acc0;
                const float* dv  = half ? dv1  : dv0;
                const int off    = half * 8;
                long long idx = plane + (long long)(ir0 + half) * W + x0;

                float g[8], mean[8], var[8], del[8];
                #pragma unroll
                for (int i = 0; i < 8; ++i) {
                    g[i] = clampg(acc[i]);
                    float s  = sumA[off + i] + g[i];
                    float sq = fmaf(g[i], g[i], ssqA[off + i]);
                    mean[i] = s * inv;
                    var[i]  = fmaf(-mean[i], mean[i], sq * inv);
                    del[i]  = g[i] - dv[i];
                }
                *reinterpret_cast<float4*>(out + idx)                = make_float4(g[0], g[1], g[2], g[3]);
                *reinterpret_cast<float4*>(out + idx + 4)            = make_float4(g[4], g[5], g[6], g[7]);
                *reinterpret_cast<float4*>(out + NTOT + idx)         = make_float4(mean[0], mean[1], mean[2], mean[3]);
                *reinterpret_cast<float4*>(out + NTOT + idx + 4)     = make_float4(mean[4], mean[5], mean[6], mean[7]);
                *reinterpret_cast<float4*>(out + 2 * NTOT + idx)     = make_float4(var[0], var[1], var[2], var[3]);
                *reinterpret_cast<float4*>(out + 2 * NTOT + idx + 4) = make_float4(var[4], var[5], var[6], var[7]);
                *reinterpret_cast<float4*>(out + 3 * NTOT + idx)     = make_float4(del[0], del[1], del[2], del[3]);
                *reinterpret_cast<float4*>(out + 3 * NTOT + idx + 4) = make_float4(del[4], del[5], del[6], del[7]);
                *reinterpret_cast<float4*>(out + 4 * NTOT + idx)     = make_float4(del[0], del[1], del[2], del[3]);
                *reinterpret_cast<float4*>(out + 4 * NTOT + idx + 4) = make_float4(del[4], del[5], del[6], del[7]);
            }
        }
    }
}

extern "C" void kernel_launch(void* const* d_in, const int* in_sizes, int n_in,
                              void* d_out, int out_size)
{
    const float* drive  = (const float*)d_in[0];   // [16,8,256,256] f32
    const float* Klocal = (const float*)d_in[1];   // [8,1,3,3] f32
    float* out = (float*)d_out;                    // 5 x [16,8,256,256] f32

    const int smem_bytes = 2 * BROWS * W * (int)sizeof(float);   // 196608
    cudaFuncSetAttribute(cml_fused_kernel,
                         cudaFuncAttributeMaxDynamicSharedMemorySize, smem_bytes);

    dim3 grid(HIMG / STRIP, 8, 16);    // 4 strips x 8 ch x 16 batch = 512 CTAs
    dim3 block(TXN, TYN);              // 512 threads
    cml_fused_kernel<<<grid, block, smem_bytes>>>(drive, Klocal, out);
}